// round 10
// baseline (speedup 1.0000x reference)
#include <cuda_runtime.h>
#include <cuda_fp16.h>
#include <cstdint>

// ============================ problem constants ============================
#define Bn      8
#define Np      16384
#define MCc     2048
#define KNNk    32
#define EMBc    256
#define MT      4                 // m-tiles per group (M = 128 rows)
#define NGROUPS (Bn * MCc / MT)   // 4096
#define GRID    152
#define NT      512

// Strides in halfs, padded so row byte-stride mod 128 == 16 -> ldmatrix /
// stmatrix 8-row sets conflict-free.
#define PKH  136                  // h2 and W3 k-stride (K=128)
#define PKW  72                   // W2 k-stride (K=64)
#define H2SZ 34816                // one h2 buffer: 128*136*2 B

// SMEM byte offsets (16B aligned)
#define S_W3  0                              // [256][136] half: 69632 B
#define S_H2  69632                          // 2 buffers x 34816 B
#define S_W2  139264                         // [128][72]  half: 18432 B
#define S_B2  157696                         // 128 f32
#define S_W1  158208                         // 192 f32
#define S_B1  158976                         // 64 f32
#define SMEM_BYTES 159232

// ============================ PTX helpers ============================
__device__ __forceinline__ void mma16(float* d, const uint32_t* a,
                                      uint32_t b0, uint32_t b1) {
    asm volatile(
        "mma.sync.aligned.m16n8k16.row.col.f32.f16.f16.f32 "
        "{%0,%1,%2,%3}, {%4,%5,%6,%7}, {%8,%9}, {%0,%1,%2,%3};"
        : "+f"(d[0]), "+f"(d[1]), "+f"(d[2]), "+f"(d[3])
        : "r"(a[0]), "r"(a[1]), "r"(a[2]), "r"(a[3]), "r"(b0), "r"(b1));
}

__device__ __forceinline__ void ldsm4(uint32_t* r, uint32_t addr) {
    asm volatile(
        "ldmatrix.sync.aligned.m8n8.x4.shared.b16 {%0,%1,%2,%3}, [%4];"
        : "=r"(r[0]), "=r"(r[1]), "=r"(r[2]), "=r"(r[3]) : "r"(addr));
}

__device__ __forceinline__ void stsm4(uint32_t addr, uint32_t r0, uint32_t r1,
                                      uint32_t r2, uint32_t r3) {
    asm volatile(
        "stmatrix.sync.aligned.m8n8.x4.shared.b16 [%0], {%1,%2,%3,%4};"
        :: "r"(addr), "r"(r0), "r"(r1), "r"(r2), "r"(r3) : "memory");
}

__device__ __forceinline__ uint32_t smem_u32(const void* p) {
    uint32_t a;
    asm("{ .reg .u64 t; cvta.to.shared.u64 t, %1; cvt.u32.u64 %0, t; }"
        : "=r"(a) : "l"(p));
    return a;
}

__device__ __forceinline__ uint32_t packh2(float a, float b) {
    __half2 h = __floats2half2_rn(a, b);
    return *reinterpret_cast<uint32_t*>(&h);
}

__device__ __forceinline__ void quad_bar(int id) {
    asm volatile("bar.sync %0, %1;" :: "r"(id), "r"(128) : "memory");
}

// ============================ kernel ============================
__global__ __launch_bounds__(NT, 1)
void patch_embed_mma(const float* __restrict__ xyz,
                     const float* __restrict__ centers,
                     const int*   __restrict__ idx_knn,
                     const float* __restrict__ W1,
                     const float* __restrict__ b1,
                     const float* __restrict__ W2,
                     const float* __restrict__ b2,
                     const float* __restrict__ W3,
                     const float* __restrict__ b3,
                     float*       __restrict__ out)
{
    extern __shared__ __align__(16) char smem[];
    __half* sW3h = reinterpret_cast<__half*>(smem + S_W3);
    __half* sW2h = reinterpret_cast<__half*>(smem + S_W2);
    float*  sB2  = reinterpret_cast<float*>(smem + S_B2);
    float*  sW1v = reinterpret_cast<float*>(smem + S_W1);
    float*  sB1v = reinterpret_cast<float*>(smem + S_B1);

    const int tid  = threadIdx.x;
    const int lane = tid & 31;
    const int wid  = tid >> 5;
    const int gp   = lane >> 2;
    const int tg   = lane & 3;

    // quad pipelines: mtp = m-block (quad id), nq = n quarter within quad.
    const int mtp = wid >> 2;
    const int nq  = wid & 3;
    const int bar = mtp + 1;

    // ---- one-time staging: fp16 weights ------------------------------------
    for (int i = tid; i < 256 * 128; i += NT) {       // W3 [n=256][k=128]
        int n = i >> 7, k = i & 127;
        sW3h[n * PKH + k] = __float2half_rn(W3[i]);
    }
    for (int i = tid; i < 128 * 64; i += NT) {        // W2 [n=128][k=64]
        int n = i >> 6, k = i & 63;
        sW2h[n * PKW + k] = __float2half_rn(W2[i]);
    }
    if (tid < 192) sW1v[tid] = W1[tid];
    if (tid < 64)  sB1v[tid] = b1[tid];
    if (tid < 128) sB2[tid]  = b2[tid];
    __syncthreads();

    // ---- precomputed smem addresses (bytes) --------------------------------
    const uint32_t sH2_b = smem_u32(smem + S_H2);
    const uint32_t sW3_b = smem_u32(sW3h);
    const uint32_t sW2_b = smem_u32(sW2h);
    // A frags (h2): rows mtp*32 + m*16 + (lane&15), k-half (lane>>4)*8
    uint32_t a2Addr[2];
    #pragma unroll
    for (int m = 0; m < 2; ++m)
        a2Addr[m] = sH2_b +
            (((mtp*32 + m*16 + (lane & 15)) * PKH + ((lane >> 4) << 3)) << 1);
    // B (W3): n = nq*64 + p*16 + (lane&7) + ((lane>>4)<<3); k-half ((lane>>3)&1)*8
    uint32_t b3Addr[4];
    #pragma unroll
    for (int p = 0; p < 4; ++p)
        b3Addr[p] = sW3_b +
            (((nq*64 + p*16 + (lane & 7) + ((lane >> 4) << 3)) * PKH
              + (((lane >> 3) & 1) << 3)) << 1);
    // B (W2): n = nq*32 + p*16 + ...
    uint32_t b2Addr[2];
    #pragma unroll
    for (int p = 0; p < 2; ++p)
        b2Addr[p] = sW2_b +
            (((nq*32 + p*16 + (lane & 7) + ((lane >> 4) << 3)) * PKW
              + (((lane >> 3) & 1) << 3)) << 1);
    // stmatrix (h2 epi): instruction (m, p) stores tiles nt=2p,2p+1 of m-tile m.
    // lane -> matrix (lane>>3): row += (mat&1)*8, col += (mat>>1)*8.
    uint32_t stAddr[2][2];
    #pragma unroll
    for (int m = 0; m < 2; ++m)
        #pragma unroll
        for (int p = 0; p < 2; ++p) {
            const int mat = lane >> 3, rin = lane & 7;
            const int r = mtp*32 + m*16 + (mat & 1)*8 + rin;
            const int c = nq*32 + p*16 + (mat >> 1)*8;
            stAddr[m][p] = sH2_b + ((r * PKH + c) << 1);
        }

    // ---- gather state: 4 rows per thread = knn indices gp + 8j of bm -------
    float px[4], py[4], pz[4];
    {
        const int bm = blockIdx.x * MT + mtp;
        const float cx = __ldg(&centers[bm*3 + 0]);
        const float cy = __ldg(&centers[bm*3 + 1]);
        const float cz = __ldg(&centers[bm*3 + 2]);
        #pragma unroll
        for (int j = 0; j < 4; ++j) {
            const int ii = __ldg(&idx_knn[bm * KNNk + gp + 8*j]);
            const float* p = xyz + ((size_t)(bm >> 11) * Np + ii) * 3;
            px[j] = p[0] - cx; py[j] = p[1] - cy; pz[j] = p[2] - cz;
        }
    }

    int it = 0;
    for (int g = blockIdx.x; g < NGROUPS; g += GRID, ++it) {
        const uint32_t hoff = (it & 1) ? (uint32_t)H2SZ : 0u;

        // ---- fused layer 1: build GEMM1 A-frags in registers ---------------
        // af[ks][m][i]: thread's m16n8k16 A fragment, rows gp+8j (j=2m+half),
        // channels 2tg + 8q (+1), q = 2ks + (i>>1).
        uint32_t af[4][2][4];
        #pragma unroll
        for (int q = 0; q < 8; ++q) {
            const int c0 = 2*tg + 8*q;
            const float w00 = sW1v[c0*3+0], w01 = sW1v[c0*3+1], w02 = sW1v[c0*3+2];
            const float w10 = sW1v[c0*3+3], w11 = sW1v[c0*3+4], w12 = sW1v[c0*3+5];
            const float bb0 = sB1v[c0], bb1 = sB1v[c0+1];
            #pragma unroll
            for (int j = 0; j < 4; ++j) {
                float v0 = fmaf(w02, pz[j], fmaf(w01, py[j], fmaf(w00, px[j], bb0)));
                float v1 = fmaf(w12, pz[j], fmaf(w11, py[j], fmaf(w10, px[j], bb1)));
                af[q>>1][j>>1][((q & 1) << 1) + (j & 1)] =
                    packh2(fmaxf(v0, 0.f), fmaxf(v1, 0.f));
            }
        }

        // prefetch next group's knn indices (overlaps GEMM1)
        const int gn  = (g + GRID < NGROUPS) ? (g + GRID) : g;
        const int nbm = gn * MT + mtp;
        int nidx[4];
        #pragma unroll
        for (int j = 0; j < 4; ++j)
            nidx[j] = __ldg(&idx_knn[nbm * KNNk + gp + 8*j]);

        // ---- GEMM1: no barrier needed (A in regs, W2 read-only) ------------
        float acc1[2][4][4];
        #pragma unroll
        for (int m = 0; m < 2; ++m)
            #pragma unroll
            for (int nt = 0; nt < 4; ++nt)
                #pragma unroll
                for (int j = 0; j < 4; ++j) acc1[m][nt][j] = 0.f;

        #pragma unroll
        for (int ks = 0; ks < 4; ++ks) {
            const uint32_t k4 = (uint32_t)ks << 5;
            #pragma unroll
            for (int p = 0; p < 2; ++p) {
                uint32_t bf[4];
                ldsm4(bf, b2Addr[p] + k4);
                mma16(acc1[0][2*p],     af[ks][0], bf[0], bf[1]);
                mma16(acc1[1][2*p],     af[ks][1], bf[0], bf[1]);
                mma16(acc1[0][2*p + 1], af[ks][0], bf[2], bf[3]);
                mma16(acc1[1][2*p + 1], af[ks][1], bf[2], bf[3]);
            }
        }

        // ---- epilogue 1: h2 = fp16(relu(D1 + b2)) via stmatrix -------------
        #pragma unroll
        for (int m = 0; m < 2; ++m)
            #pragma unroll
            for (int p = 0; p < 2; ++p) {
                uint32_t rr[2][2];   // [nt-half][lo/hi]
                #pragma unroll
                for (int h = 0; h < 2; ++h) {
                    const int nt = 2*p + h;
                    const int c0 = nq*32 + nt*8 + 2*tg;
                    const float bb0 = sB2[c0], bb1 = sB2[c0 + 1];
                    rr[h][0] = packh2(fmaxf(acc1[m][nt][0] + bb0, 0.f),
                                      fmaxf(acc1[m][nt][1] + bb1, 0.f));
                    rr[h][1] = packh2(fmaxf(acc1[m][nt][2] + bb0, 0.f),
                                      fmaxf(acc1[m][nt][3] + bb1, 0.f));
                }
                stsm4(stAddr[m][p] + hoff, rr[0][0], rr[0][1], rr[1][0], rr[1][1]);
            }

        // prefetch next group's coords (overlaps GEMM2)
        {
            const float cx = __ldg(&centers[nbm*3 + 0]);
            const float cy = __ldg(&centers[nbm*3 + 1]);
            const float cz = __ldg(&centers[nbm*3 + 2]);
            #pragma unroll
            for (int j = 0; j < 4; ++j) {
                const float* p = xyz + ((size_t)(nbm >> 11) * Np + nidx[j]) * 3;
                px[j] = p[0] - cx; py[j] = p[1] - cy; pz[j] = p[2] - cz;
            }
        }

        quad_bar(bar);   // quad's h2 writes visible before GEMM2 reads

        // ---- GEMM2: D2[m-block x 256] = h2 * W3^T  (8 k16 steps) -----------
        {
            float acc2[2][8][4];
            #pragma unroll
            for (int m = 0; m < 2; ++m)
                #pragma unroll
                for (int nt = 0; nt < 8; ++nt)
                    #pragma unroll
                    for (int j = 0; j < 4; ++j) acc2[m][nt][j] = 0.f;

            #pragma unroll
            for (int ks = 0; ks < 8; ++ks) {
                const uint32_t k4 = (uint32_t)ks << 5;
                uint32_t a0[4], a1[4];
                ldsm4(a0, a2Addr[0] + hoff + k4);
                ldsm4(a1, a2Addr[1] + hoff + k4);
                #pragma unroll
                for (int p = 0; p < 4; ++p) {
                    uint32_t bf[4];
                    ldsm4(bf, b3Addr[p] + k4);
                    mma16(acc2[0][2*p],     a0, bf[0], bf[1]);
                    mma16(acc2[1][2*p],     a1, bf[0], bf[1]);
                    mma16(acc2[0][2*p + 1], a0, bf[2], bf[3]);
                    mma16(acc2[1][2*p + 1], a1, bf[2], bf[3]);
                }
            }

            // ---- max over 32 k-rows of this warp's m-block + b3 + store ----
            const int bm = g * MT + mtp;
            #pragma unroll
            for (int nt = 0; nt < 8; ++nt) {
                float m0 = fmaxf(fmaxf(acc2[0][nt][0], acc2[0][nt][2]),
                                 fmaxf(acc2[1][nt][0], acc2[1][nt][2]));
                float m1 = fmaxf(fmaxf(acc2[0][nt][1], acc2[0][nt][3]),
                                 fmaxf(acc2[1][nt][1], acc2[1][nt][3]));
                #pragma unroll
                for (int s = 4; s < 32; s <<= 1) {
                    m0 = fmaxf(m0, __shfl_xor_sync(0xffffffffu, m0, s));
                    m1 = fmaxf(m1, __shfl_xor_sync(0xffffffffu, m1, s));
                }
                if (lane < 4) {
                    const int c = nq*64 + nt*8 + 2*tg;
                    float2 r2;
                    r2.x = m0 + __ldg(&b3[c]);
                    r2.y = m1 + __ldg(&b3[c + 1]);
                    *reinterpret_cast<float2*>(&out[(size_t)bm * EMBc + c]) = r2;
                }
            }
        }
        // no trailing barrier: next epi1 writes the OTHER h2 buffer; the
        // conflicting pair (peer GEMM2(g-1) reads vs my epi1(g+1) writes of
        // the same buffer) is separated by quad_bar(g).
    }
}

// ============================ launch ============================
extern "C" void kernel_launch(void* const* d_in, const int* in_sizes, int n_in,
                              void* d_out, int out_size)
{
    // metadata order: xyz, centers, idx_knn, W1, b1, W2, b2, W3, b3
    const float* xyz     = (const float*)d_in[0];
    const float* centers = (const float*)d_in[1];
    const int*   idx_knn = (const int*)  d_in[2];
    const float* W1      = (const float*)d_in[3];
    const float* b1      = (const float*)d_in[4];
    const float* W2      = (const float*)d_in[5];
    const float* b2      = (const float*)d_in[6];
    const float* W3      = (const float*)d_in[7];
    const float* b3      = (const float*)d_in[8];
    float* out = (float*)d_out;

    // Idempotent attribute set (capture-safe, no allocation).
    cudaFuncSetAttribute(patch_embed_mma,
                         cudaFuncAttributeMaxDynamicSharedMemorySize,
                         SMEM_BYTES);

    patch_embed_mma<<<GRID, NT, SMEM_BYTES>>>(
        xyz, centers, idx_knn, W1, b1, W2, b2, W3, b3, out);
}

// round 11
// speedup vs baseline: 1.0222x; 1.0222x over previous
#include <cuda_runtime.h>
#include <cuda_fp16.h>
#include <cstdint>

// ============================ problem constants ============================
#define Bn      8
#define Np      16384
#define MCc     2048
#define KNNk    32
#define EMBc    256
#define MT      4                 // m-tiles per group (M = 128 rows)
#define NGROUPS (Bn * MCc / MT)   // 4096
#define GRID    152
#define NT      512

// Strides in halfs, padded so ldmatrix/stmatrix 8-row sets are conflict-free.
#define PKH  136                  // h2 and W3 k-stride (K=128): 272 B rows
#define PKW  72                   // W2 k-stride (K=64)
#define PKW1 24                   // W1ext k-stride (K=16): 48 B rows
#define H2SZ 34816                // one h2 buffer: 128*136*2 B

// SMEM byte offsets (16B aligned)
#define S_W3  0                              // [256][136] half: 69632 B
#define S_H2  69632                          // 2 buffers x 34816 B
#define S_W2  139264                         // [128][72]  half: 18432 B
#define S_W1E 157696                         // [64][24]   half: 3072 B
#define S_B2  160768                         // 128 f32
#define SMEM_BYTES 161280

// ============================ PTX helpers ============================
__device__ __forceinline__ void mma16(float* d, const uint32_t* a,
                                      uint32_t b0, uint32_t b1) {
    asm volatile(
        "mma.sync.aligned.m16n8k16.row.col.f32.f16.f16.f32 "
        "{%0,%1,%2,%3}, {%4,%5,%6,%7}, {%8,%9}, {%0,%1,%2,%3};"
        : "+f"(d[0]), "+f"(d[1]), "+f"(d[2]), "+f"(d[3])
        : "r"(a[0]), "r"(a[1]), "r"(a[2]), "r"(a[3]), "r"(b0), "r"(b1));
}

__device__ __forceinline__ void ldsm4(uint32_t* r, uint32_t addr) {
    asm volatile(
        "ldmatrix.sync.aligned.m8n8.x4.shared.b16 {%0,%1,%2,%3}, [%4];"
        : "=r"(r[0]), "=r"(r[1]), "=r"(r[2]), "=r"(r[3]) : "r"(addr));
}

__device__ __forceinline__ void stsm4(uint32_t addr, uint32_t r0, uint32_t r1,
                                      uint32_t r2, uint32_t r3) {
    asm volatile(
        "stmatrix.sync.aligned.m8n8.x4.shared.b16 [%0], {%1,%2,%3,%4};"
        :: "r"(addr), "r"(r0), "r"(r1), "r"(r2), "r"(r3) : "memory");
}

__device__ __forceinline__ uint32_t smem_u32(const void* p) {
    uint32_t a;
    asm("{ .reg .u64 t; cvta.to.shared.u64 t, %1; cvt.u32.u64 %0, t; }"
        : "=r"(a) : "l"(p));
    return a;
}

__device__ __forceinline__ uint32_t packh2(float a, float b) {
    __half2 h = __floats2half2_rn(a, b);
    return *reinterpret_cast<uint32_t*>(&h);
}

__device__ __forceinline__ void quad_bar(int id) {
    asm volatile("bar.sync %0, %1;" :: "r"(id), "r"(128) : "memory");
}

// ============================ kernel ============================
__global__ __launch_bounds__(NT, 1)
void patch_embed_mma(const float* __restrict__ xyz,
                     const float* __restrict__ centers,
                     const int*   __restrict__ idx_knn,
                     const float* __restrict__ W1,
                     const float* __restrict__ b1,
                     const float* __restrict__ W2,
                     const float* __restrict__ b2,
                     const float* __restrict__ W3,
                     const float* __restrict__ b3,
                     float*       __restrict__ out)
{
    extern __shared__ __align__(16) char smem[];
    __half* sW3h = reinterpret_cast<__half*>(smem + S_W3);
    __half* sW2h = reinterpret_cast<__half*>(smem + S_W2);
    __half* sW1e = reinterpret_cast<__half*>(smem + S_W1E);
    float*  sB2  = reinterpret_cast<float*>(smem + S_B2);

    const int tid  = threadIdx.x;
    const int lane = tid & 31;
    const int wid  = tid >> 5;
    const int gp   = lane >> 2;
    const int tg   = lane & 3;

    // quad pipelines: mtp = m-block (quad id), nq = n quarter within quad.
    const int mtp = wid >> 2;
    const int nq  = wid & 3;
    const int bar = mtp + 1;

    // ---- one-time staging: fp16 weights ------------------------------------
    for (int i = tid; i < 256 * 128; i += NT) {       // W3 [n=256][k=128]
        int n = i >> 7, k = i & 127;
        sW3h[n * PKH + k] = __float2half_rn(W3[i]);
    }
    for (int i = tid; i < 128 * 64; i += NT) {        // W2 [n=128][k=64]
        int n = i >> 6, k = i & 63;
        sW2h[n * PKW + k] = __float2half_rn(W2[i]);
    }
    for (int i = tid; i < 64 * 16; i += NT) {         // W1ext [n=64][k=16]
        int n = i >> 4, k = i & 15;
        float v = (k < 3) ? W1[n * 3 + k] : (k == 3 ? b1[n] : 0.f);
        sW1e[n * PKW1 + k] = __float2half_rn(v);
    }
    if (tid < 128) sB2[tid] = b2[tid];
    __syncthreads();

    // ---- precomputed smem addresses (bytes) --------------------------------
    const uint32_t sH2_b = smem_u32(smem + S_H2);
    const uint32_t sW3_b = smem_u32(sW3h);
    const uint32_t sW2_b = smem_u32(sW2h);
    const uint32_t sW1_b = smem_u32(sW1e);
    // A frags (h2): rows mtp*32 + m*16 + (lane&15), k-half (lane>>4)*8
    uint32_t a2Addr[2];
    #pragma unroll
    for (int m = 0; m < 2; ++m)
        a2Addr[m] = sH2_b +
            (((mtp*32 + m*16 + (lane & 15)) * PKH + ((lane >> 4) << 3)) << 1);
    // B (W3): n = nq*64 + p*16 + (lane&7) + ((lane>>4)<<3); k-half ((lane>>3)&1)*8
    uint32_t b3Addr[4];
    #pragma unroll
    for (int p = 0; p < 4; ++p)
        b3Addr[p] = sW3_b +
            (((nq*64 + p*16 + (lane & 7) + ((lane >> 4) << 3)) * PKH
              + (((lane >> 3) & 1) << 3)) << 1);
    // B (W2): n = nq*32 + p*16 + ...
    uint32_t b2Addr[2];
    #pragma unroll
    for (int p = 0; p < 2; ++p)
        b2Addr[p] = sW2_b +
            (((nq*32 + p*16 + (lane & 7) + ((lane >> 4) << 3)) * PKW
              + (((lane >> 3) & 1) << 3)) << 1);
    // B (W1ext): n = p*16 + ...  (all warps load all 64 channels)
    uint32_t b1Addr[4];
    #pragma unroll
    for (int p = 0; p < 4; ++p)
        b1Addr[p] = sW1_b +
            (((p*16 + (lane & 7) + ((lane >> 4) << 3)) * PKW1
              + (((lane >> 3) & 1) << 3)) << 1);
    // stmatrix (h2 epi)
    uint32_t stAddr[2][2];
    #pragma unroll
    for (int m = 0; m < 2; ++m)
        #pragma unroll
        for (int p = 0; p < 2; ++p) {
            const int mat = lane >> 3, rin = lane & 7;
            const int r = mtp*32 + m*16 + (mat & 1)*8 + rin;
            const int c = nq*32 + p*16 + (mat >> 1)*8;
            stAddr[m][p] = sH2_b + ((r * PKH + c) << 1);
        }

    // ---- hoisted W1ext B-fragments (loop-invariant, 16 regs) ---------------
    uint32_t bW1[4][4];
    #pragma unroll
    for (int p = 0; p < 4; ++p) ldsm4(bW1[p], b1Addr[p]);

    // ---- gather state: 4 rows per thread = knn indices gp + 8j of bm -------
    float px[4], py[4], pz[4];
    {
        const int bm = blockIdx.x * MT + mtp;
        const float cx = __ldg(&centers[bm*3 + 0]);
        const float cy = __ldg(&centers[bm*3 + 1]);
        const float cz = __ldg(&centers[bm*3 + 2]);
        #pragma unroll
        for (int j = 0; j < 4; ++j) {
            const int ii = __ldg(&idx_knn[bm * KNNk + gp + 8*j]);
            const float* p = xyz + ((size_t)(bm >> 11) * Np + ii) * 3;
            px[j] = p[0] - cx; py[j] = p[1] - cy; pz[j] = p[2] - cz;
        }
    }

    int it = 0;
    for (int g = blockIdx.x; g < NGROUPS; g += GRID, ++it) {
        const uint32_t hoff = (it & 1) ? (uint32_t)H2SZ : 0u;

        // ---- layer 1 as MMA0: h1-frags born in registers -------------------
        // A = [x,y,z,1] (K=16, only k<4 nonzero): a0/a1 from coords, a2/a3=0.
        // C-frag (row gp, cols 2tg..) == A-frag layout of GEMM1 -> direct
        // relu+pack conversion, no smem round-trip.
        uint32_t af[4][2][4];
        #pragma unroll
        for (int m = 0; m < 2; ++m) {
            const int j0 = 2*m, j1 = 2*m + 1;
            uint32_t a[4];
            a[0] = (tg == 0) ? packh2(px[j0], py[j0])
                 : (tg == 1) ? packh2(pz[j0], 1.f) : 0u;
            a[1] = (tg == 0) ? packh2(px[j1], py[j1])
                 : (tg == 1) ? packh2(pz[j1], 1.f) : 0u;
            a[2] = 0u; a[3] = 0u;

            float acc0[8][4];
            #pragma unroll
            for (int nt = 0; nt < 8; ++nt)
                #pragma unroll
                for (int j = 0; j < 4; ++j) acc0[nt][j] = 0.f;
            #pragma unroll
            for (int p = 0; p < 4; ++p) {
                mma16(acc0[2*p],     a, bW1[p][0], bW1[p][1]);
                mma16(acc0[2*p + 1], a, bW1[p][2], bW1[p][3]);
            }
            #pragma unroll
            for (int ks = 0; ks < 4; ++ks) {
                af[ks][m][0] = packh2(fmaxf(acc0[2*ks][0], 0.f),
                                      fmaxf(acc0[2*ks][1], 0.f));
                af[ks][m][1] = packh2(fmaxf(acc0[2*ks][2], 0.f),
                                      fmaxf(acc0[2*ks][3], 0.f));
                af[ks][m][2] = packh2(fmaxf(acc0[2*ks+1][0], 0.f),
                                      fmaxf(acc0[2*ks+1][1], 0.f));
                af[ks][m][3] = packh2(fmaxf(acc0[2*ks+1][2], 0.f),
                                      fmaxf(acc0[2*ks+1][3], 0.f));
            }
        }

        // prefetch next group's knn indices (overlaps GEMM1)
        const int gn  = (g + GRID < NGROUPS) ? (g + GRID) : g;
        const int nbm = gn * MT + mtp;
        int nidx[4];
        #pragma unroll
        for (int j = 0; j < 4; ++j)
            nidx[j] = __ldg(&idx_knn[nbm * KNNk + gp + 8*j]);

        // ---- GEMM1: no barrier needed (A in regs, W2 read-only) ------------
        float acc1[2][4][4];
        #pragma unroll
        for (int m = 0; m < 2; ++m)
            #pragma unroll
            for (int nt = 0; nt < 4; ++nt)
                #pragma unroll
                for (int j = 0; j < 4; ++j) acc1[m][nt][j] = 0.f;

        #pragma unroll
        for (int ks = 0; ks < 4; ++ks) {
            const uint32_t k4 = (uint32_t)ks << 5;
            #pragma unroll
            for (int p = 0; p < 2; ++p) {
                uint32_t bf[4];
                ldsm4(bf, b2Addr[p] + k4);
                mma16(acc1[0][2*p],     af[ks][0], bf[0], bf[1]);
                mma16(acc1[1][2*p],     af[ks][1], bf[0], bf[1]);
                mma16(acc1[0][2*p + 1], af[ks][0], bf[2], bf[3]);
                mma16(acc1[1][2*p + 1], af[ks][1], bf[2], bf[3]);
            }
        }

        // ---- epilogue 1: h2 = fp16(relu(D1 + b2)) via stmatrix -------------
        #pragma unroll
        for (int m = 0; m < 2; ++m)
            #pragma unroll
            for (int p = 0; p < 2; ++p) {
                uint32_t rr[2][2];
                #pragma unroll
                for (int h = 0; h < 2; ++h) {
                    const int nt = 2*p + h;
                    const int c0 = nq*32 + nt*8 + 2*tg;
                    const float bb0 = sB2[c0], bb1 = sB2[c0 + 1];
                    rr[h][0] = packh2(fmaxf(acc1[m][nt][0] + bb0, 0.f),
                                      fmaxf(acc1[m][nt][1] + bb1, 0.f));
                    rr[h][1] = packh2(fmaxf(acc1[m][nt][2] + bb0, 0.f),
                                      fmaxf(acc1[m][nt][3] + bb1, 0.f));
                }
                stsm4(stAddr[m][p] + hoff, rr[0][0], rr[0][1], rr[1][0], rr[1][1]);
            }

        // prefetch next group's coords (overlaps GEMM2)
        {
            const float cx = __ldg(&centers[nbm*3 + 0]);
            const float cy = __ldg(&centers[nbm*3 + 1]);
            const float cz = __ldg(&centers[nbm*3 + 2]);
            #pragma unroll
            for (int j = 0; j < 4; ++j) {
                const float* p = xyz + ((size_t)(nbm >> 11) * Np + nidx[j]) * 3;
                px[j] = p[0] - cx; py[j] = p[1] - cy; pz[j] = p[2] - cz;
            }
        }

        quad_bar(bar);   // quad's h2 writes visible before GEMM2 reads

        // ---- GEMM2: D2[m-block x 256] = h2 * W3^T  (8 k16 steps) -----------
        {
            float acc2[2][8][4];
            #pragma unroll
            for (int m = 0; m < 2; ++m)
                #pragma unroll
                for (int nt = 0; nt < 8; ++nt)
                    #pragma unroll
                    for (int j = 0; j < 4; ++j) acc2[m][nt][j] = 0.f;

            #pragma unroll
            for (int ks = 0; ks < 8; ++ks) {
                const uint32_t k4 = (uint32_t)ks << 5;
                uint32_t a0[4], a1[4];
                ldsm4(a0, a2Addr[0] + hoff + k4);
                ldsm4(a1, a2Addr[1] + hoff + k4);
                #pragma unroll
                for (int p = 0; p < 4; ++p) {
                    uint32_t bf[4];
                    ldsm4(bf, b3Addr[p] + k4);
                    mma16(acc2[0][2*p],     a0, bf[0], bf[1]);
                    mma16(acc2[1][2*p],     a1, bf[0], bf[1]);
                    mma16(acc2[0][2*p + 1], a0, bf[2], bf[3]);
                    mma16(acc2[1][2*p + 1], a1, bf[2], bf[3]);
                }
            }

            // ---- max over 32 k-rows of this warp's m-block + b3 + store ----
            const int bm = g * MT + mtp;
            #pragma unroll
            for (int nt = 0; nt < 8; ++nt) {
                float m0 = fmaxf(fmaxf(acc2[0][nt][0], acc2[0][nt][2]),
                                 fmaxf(acc2[1][nt][0], acc2[1][nt][2]));
                float m1 = fmaxf(fmaxf(acc2[0][nt][1], acc2[0][nt][3]),
                                 fmaxf(acc2[1][nt][1], acc2[1][nt][3]));
                #pragma unroll
                for (int s = 4; s < 32; s <<= 1) {
                    m0 = fmaxf(m0, __shfl_xor_sync(0xffffffffu, m0, s));
                    m1 = fmaxf(m1, __shfl_xor_sync(0xffffffffu, m1, s));
                }
                if (lane < 4) {
                    const int c = nq*64 + nt*8 + 2*tg;
                    float2 r2;
                    r2.x = m0 + __ldg(&b3[c]);
                    r2.y = m1 + __ldg(&b3[c + 1]);
                    *reinterpret_cast<float2*>(&out[(size_t)bm * EMBc + c]) = r2;
                }
            }
        }
        // no trailing barrier: next epi1 writes the OTHER h2 buffer; the
        // conflicting pair (peer GEMM2(g-1) reads vs my epi1(g+1) writes of
        // the same buffer) is separated by quad_bar(g).
    }
}

// ============================ launch ============================
extern "C" void kernel_launch(void* const* d_in, const int* in_sizes, int n_in,
                              void* d_out, int out_size)
{
    // metadata order: xyz, centers, idx_knn, W1, b1, W2, b2, W3, b3
    const float* xyz     = (const float*)d_in[0];
    const float* centers = (const float*)d_in[1];
    const int*   idx_knn = (const int*)  d_in[2];
    const float* W1      = (const float*)d_in[3];
    const float* b1      = (const float*)d_in[4];
    const float* W2      = (const float*)d_in[5];
    const float* b2      = (const float*)d_in[6];
    const float* W3      = (const float*)d_in[7];
    const float* b3      = (const float*)d_in[8];
    float* out = (float*)d_out;

    // Idempotent attribute set (capture-safe, no allocation).
    cudaFuncSetAttribute(patch_embed_mma,
                         cudaFuncAttributeMaxDynamicSharedMemorySize,
                         SMEM_BYTES);

    patch_embed_mma<<<GRID, NT, SMEM_BYTES>>>(
        xyz, centers, idx_knn, W1, b1, W2, b2, W3, b3, out);
}